// round 16
// baseline (speedup 1.0000x reference)
#include <cuda_runtime.h>
#include <cuda_bf16.h>
#include <math.h>
#include <stdint.h>

// ===========================================================================
// ZorroPP reduced:
//   mu[c] = g[c]*((1-l)*rowmean(sk[c,:]) + (1/t)*g[c]*colsum_x[c]*(C/M) + 0.01*rowmean(noise[c,:]))
//   out   = (s*x) @ W - s*(mu^T W) + b      (rank-1 mu correction pulled out)
// GEMM: HMMA m16n8k16 bf16 hi/lo split (3 products) = emulated fp32.
// TWO kernels total:
//   prep : W->W^T hi/lo, x*s hi/lo, zero r + counters
//   fused: 128 GEMM blocks (3-stage, KCH=16) + 128 mu blocks (ldcs + r-slice).
//          Last K-split block per (bm,bn) group combines into out directly.
// ===========================================================================

#define BDIM 512
#define CDIM 4096
#define NDIM 1000
#define NPAD 1024
#define MSK  8192
#define KSPLIT 4
#define KSLICE (CDIM / KSPLIT)   // 1024
#define KCH 16
#define NC (KSLICE / KCH)        // 64 chunks per gemm block

__device__ float g_r[NPAD];                      // s * mu^T W (atomic accum)
__device__ __nv_bfloat16 g_xhi[BDIM * CDIM];
__device__ __nv_bfloat16 g_xlo[BDIM * CDIM];
__device__ __nv_bfloat16 g_wthi[NPAD * CDIM];
__device__ __nv_bfloat16 g_wtlo[NPAD * CDIM];
__device__ float g_part[KSPLIT][BDIM * NPAD];
__device__ unsigned g_cnt_grp[32];
__device__ unsigned g_cnt_r;

// ---------------------------------------------------------------------------
// PTX helpers (baseline sm_80+; compute_103-safe)
// ---------------------------------------------------------------------------
__device__ __forceinline__ uint32_t smem_u32(const void* p) {
    uint32_t a;
    asm("{ .reg .u64 t; cvta.to.shared.u64 t, %1; cvt.u32.u64 %0, t; }"
        : "=r"(a) : "l"(p));
    return a;
}
__device__ __forceinline__ void cpasync16(uint32_t sdst, const void* gsrc) {
    asm volatile("cp.async.cg.shared.global [%0], [%1], 16;"
                 :: "r"(sdst), "l"(gsrc) : "memory");
}
#define CP_COMMIT() asm volatile("cp.async.commit_group;" ::: "memory")
#define CP_WAIT2()  asm volatile("cp.async.wait_group 2;" ::: "memory")

#define LDSM4(r, addr)                                                        \
    asm volatile("ldmatrix.sync.aligned.m8n8.x4.shared.b16 {%0,%1,%2,%3}, [%4];" \
                 : "=r"((r)[0]), "=r"((r)[1]), "=r"((r)[2]), "=r"((r)[3])     \
                 : "r"(addr))

#define MMA16816(d, a, b)                                                     \
    asm volatile("mma.sync.aligned.m16n8k16.row.col.f32.bf16.bf16.f32 "      \
                 "{%0,%1,%2,%3}, {%4,%5,%6,%7}, {%8,%9}, {%0,%1,%2,%3};"     \
                 : "+f"((d)[0]), "+f"((d)[1]), "+f"((d)[2]), "+f"((d)[3])     \
                 : "r"((a)[0]), "r"((a)[1]), "r"((a)[2]), "r"((a)[3]),        \
                   "r"((b)[0]), "r"((b)[1]))

// ---------------------------------------------------------------------------
// Kernel 1 (PREP): [0,1024) W->W^T hi/lo (64x64 tiles); [1024,3072) x*s hi/lo
// First x-blocks also zero g_r and the sequencing counters (replay-safe).
// ---------------------------------------------------------------------------
__global__ __launch_bounds__(256) void prep_kernel(
    const float* __restrict__ W, const float* __restrict__ x, int N, float s)
{
    __shared__ float tile[64][65];
    int bid = blockIdx.x;
    if (bid < 1024) {
        int k0 = (bid & 63) * 64, n0 = (bid >> 6) * 64;
        int tx = threadIdx.x & 31, ty = threadIdx.x >> 5;
        #pragma unroll
        for (int r = 0; r < 8; ++r) {
            int kk = ty + r * 8;
            int col = n0 + tx * 2;
            const float* wr = W + (size_t)(k0 + kk) * N;
            tile[kk][tx * 2]     = (col < N)     ? __ldcs(&wr[col])     : 0.f;
            tile[kk][tx * 2 + 1] = (col + 1 < N) ? __ldcs(&wr[col + 1]) : 0.f;
        }
        __syncthreads();
        #pragma unroll
        for (int r = 0; r < 8; ++r) {
            int nn = ty + r * 8;
            float v0 = tile[tx * 2][nn];
            float v1 = tile[tx * 2 + 1][nn];
            __nv_bfloat16 h0 = __float2bfloat16(v0);
            __nv_bfloat16 h1 = __float2bfloat16(v1);
            __nv_bfloat16 l0 = __float2bfloat16(v0 - __bfloat162float(h0));
            __nv_bfloat16 l1 = __float2bfloat16(v1 - __bfloat162float(h1));
            size_t o = (size_t)(n0 + nn) * CDIM + k0 + tx * 2;
            *(__nv_bfloat162*)&g_wthi[o] = __halves2bfloat162(h0, h1);
            *(__nv_bfloat162*)&g_wtlo[o] = __halves2bfloat162(l0, l1);
        }
    } else {
        int xb = bid - 1024;
        if (xb < 4) g_r[xb * 256 + threadIdx.x] = 0.f;
        if (xb == 4 && threadIdx.x < 32) g_cnt_grp[threadIdx.x] = 0u;
        if (xb == 4 && threadIdx.x == 32) g_cnt_r = 0u;
        int i4 = xb * 256 + threadIdx.x;
        float4 v = ((const float4*)x)[i4];
        float a0 = v.x * s, a1 = v.y * s, a2 = v.z * s, a3 = v.w * s;
        __nv_bfloat16 h0 = __float2bfloat16(a0), h1 = __float2bfloat16(a1);
        __nv_bfloat16 h2 = __float2bfloat16(a2), h3 = __float2bfloat16(a3);
        __nv_bfloat16 l0 = __float2bfloat16(a0 - __bfloat162float(h0));
        __nv_bfloat16 l1 = __float2bfloat16(a1 - __bfloat162float(h1));
        __nv_bfloat16 l2 = __float2bfloat16(a2 - __bfloat162float(h2));
        __nv_bfloat16 l3 = __float2bfloat16(a3 - __bfloat162float(h3));
        __nv_bfloat162* ph = (__nv_bfloat162*)(g_xhi + (size_t)i4 * 4);
        __nv_bfloat162* pl = (__nv_bfloat162*)(g_xlo + (size_t)i4 * 4);
        ph[0] = __halves2bfloat162(h0, h1);
        ph[1] = __halves2bfloat162(h2, h3);
        pl[0] = __halves2bfloat162(l0, l1);
        pl[1] = __halves2bfloat162(l2, l3);
    }
}

// ---------------------------------------------------------------------------
// Kernel 2 (FUSED): blocks [0,128) = GEMM (3-stage, KCH=16) + group combine;
//                   blocks [128,256) = mu (ldcs) + r-slice atomics.
// ---------------------------------------------------------------------------
#define ROWB 48
#define TILE_B (128 * ROWB)          // 6144
#define STAGE_B (4 * TILE_B)         // 24576
#define SMEM_GEMM (3 * STAGE_B)      // 73728 -> 2 blocks/SM

__global__ __launch_bounds__(256, 2) void fused_kernel(
    const float* __restrict__ sk, const float* __restrict__ noise,
    const float* __restrict__ x, const float* __restrict__ g,
    const int* __restrict__ tptr, const float* __restrict__ bias,
    float* __restrict__ out, float s)
{
    extern __shared__ char smem[];
    const int tid = threadIdx.x, wid = tid >> 5, lane = tid & 31;
    const int bid = blockIdx.x;

    if (bid >= 128) {
        // ============ mu block: 32 channels (ldcs) + r slice ============
        const int c0 = (bid - 128) * 32;
        __shared__ float ps[8][33];
        __shared__ float colsum_s[32];
        __shared__ float mul[32];
        {   // coalesced colsum of x
            int ch = tid & 31, rg = tid >> 5;
            float cs = 0.f;
            #pragma unroll 8
            for (int r = rg; r < BDIM; r += 8)
                cs += x[(size_t)r * CDIM + c0 + ch];
            ps[rg][ch] = cs;
        }
        __syncthreads();
        if (tid < 32) {
            float v = 0.f;
            #pragma unroll
            for (int j = 0; j < 8; ++j) v += ps[j][tid];
            colsum_s[tid] = v;
        }
        __syncthreads();

        int ti = *tptr;
        float tf = (ti > 0 && ti < 1000000) ? (float)ti : __int_as_float(ti);
        float lam = 1.f - expf(-tf / 64.f);
        float kap = 1.f / tf;
        const float inv_m = 1.f / (float)MSK;
        const float mean_counts = (float)CDIM * inv_m;

        #pragma unroll
        for (int j = 0; j < 4; ++j) {
            int c = c0 + wid * 4 + j;
            const float4* sr = (const float4*)(sk + (size_t)c * MSK);
            const float4* nr = (const float4*)(noise + (size_t)c * MSK);
            float s1 = 0.f, s2 = 0.f;
            #pragma unroll 8
            for (int i = lane; i < MSK / 4; i += 32) {
                float4 a = __ldcs(&sr[i]);
                float4 b = __ldcs(&nr[i]);
                s1 += (a.x + a.y) + (a.z + a.w);
                s2 += (b.x + b.y) + (b.z + b.w);
            }
            #pragma unroll
            for (int off = 16; off > 0; off >>= 1) {
                s1 += __shfl_xor_sync(0xFFFFFFFFu, s1, off);
                s2 += __shfl_xor_sync(0xFFFFFFFFu, s2, off);
            }
            if (lane == 0) {
                float gc = g[c];
                float mean_sk = (1.f - lam) * (s1 * inv_m)
                              + kap * gc * colsum_s[wid * 4 + j] * mean_counts
                              + 0.01f * (s2 * inv_m);
                mul[wid * 4 + j] = gc * mean_sk;
            }
        }
        __syncthreads();

        // r-slice: r[n] += s * sum_{j<32} mu[c0+j]*(Whi[n][c0+j]+Wlo[n][c0+j])
        float m[32];
        #pragma unroll
        for (int j = 0; j < 32; ++j) m[j] = mul[j];
        #pragma unroll
        for (int pass = 0; pass < 4; ++pass) {
            int n = pass * 256 + tid;
            const uint4* hp = (const uint4*)(g_wthi + (size_t)n * CDIM + c0);
            const uint4* lp = (const uint4*)(g_wtlo + (size_t)n * CDIM + c0);
            float acc = 0.f;
            #pragma unroll
            for (int q = 0; q < 4; ++q) {
                uint4 h = hp[q], l = lp[q];
                float2 h0 = __bfloat1622float2(*(__nv_bfloat162*)&h.x);
                float2 h1 = __bfloat1622float2(*(__nv_bfloat162*)&h.y);
                float2 h2 = __bfloat1622float2(*(__nv_bfloat162*)&h.z);
                float2 h3 = __bfloat1622float2(*(__nv_bfloat162*)&h.w);
                float2 l0 = __bfloat1622float2(*(__nv_bfloat162*)&l.x);
                float2 l1 = __bfloat1622float2(*(__nv_bfloat162*)&l.y);
                float2 l2 = __bfloat1622float2(*(__nv_bfloat162*)&l.z);
                float2 l3 = __bfloat1622float2(*(__nv_bfloat162*)&l.w);
                const float* mq = m + q * 8;
                acc += mq[0] * (h0.x + l0.x) + mq[1] * (h0.y + l0.y)
                     + mq[2] * (h1.x + l1.x) + mq[3] * (h1.y + l1.y)
                     + mq[4] * (h2.x + l2.x) + mq[5] * (h2.y + l2.y)
                     + mq[6] * (h3.x + l3.x) + mq[7] * (h3.y + l3.y);
            }
            atomicAdd(&g_r[n], acc * s);
        }
        __threadfence();
        __syncthreads();
        if (tid == 0) atomicAdd(&g_cnt_r, 1u);
        return;
    }

    // ================= GEMM block (3-stage, KCH=16) =================
    const uint32_t sb = smem_u32(smem);
    const int g_id = bid;
    const int bn = (g_id & 7) * 128;
    const int bm = ((g_id >> 3) & 3) * 128;
    const int ks = g_id >> 5;
    const int kb0 = ks * KSLICE;

    const __nv_bfloat16* base[4] = {
        g_xhi  + (size_t)bm * CDIM + kb0,
        g_xlo  + (size_t)bm * CDIM + kb0,
        g_wthi + (size_t)bn * CDIM + kb0,
        g_wtlo + (size_t)bn * CDIM + kb0
    };
    const __nv_bfloat16* gp[4];
    uint32_t so[4];
    #pragma unroll
    for (int t = 0; t < 4; ++t) {
        int idx = t * 256 + tid;
        int tile = idx >> 8;
        int j = idx & 255;
        int row = j >> 1, seg = j & 1;
        gp[t] = base[tile] + (size_t)row * CDIM + seg * 8;
        so[t] = tile * TILE_B + row * ROWB + seg * 16;
    }

    auto issue = [&](int stage, int c) {
        uint32_t s0 = sb + stage * STAGE_B;
        #pragma unroll
        for (int t = 0; t < 4; ++t)
            cpasync16(s0 + so[t], gp[t] + c * KCH);
    };

    issue(0, 0); CP_COMMIT();
    issue(1, 1); CP_COMMIT();
    issue(2, 2); CP_COMMIT();

    const int wm = (wid >> 2) * 64;
    const int wn = (wid & 3) * 32;

    float acc[4][4][4];
    #pragma unroll
    for (int i = 0; i < 4; ++i)
        #pragma unroll
        for (int j = 0; j < 4; ++j)
            #pragma unroll
            for (int q = 0; q < 4; ++q) acc[i][j][q] = 0.f;

    const int arow = lane & 15;
    const int ak   = lane >> 4;
    const int brow = (lane & 7) + ((lane >> 4) << 3);
    const int bk   = (lane >> 3) & 1;

    for (int c = 0; c < NC; ++c) {
        int st = c % 3;
        CP_WAIT2();
        __syncthreads();

        uint32_t Ah = sb + st * STAGE_B;
        uint32_t Al = Ah + TILE_B;
        uint32_t Bh = Ah + 2 * TILE_B;
        uint32_t Bl = Ah + 3 * TILE_B;

        uint32_t bh[2][4], bl[2][4];
        #pragma unroll
        for (int p = 0; p < 2; ++p) {
            uint32_t off = (uint32_t)(wn + p * 16 + brow) * ROWB + bk * 16;
            LDSM4(bh[p], Bh + off);
            LDSM4(bl[p], Bl + off);
        }
        #pragma unroll
        for (int i = 0; i < 4; ++i) {
            uint32_t ah[4], al[4];
            uint32_t off = (uint32_t)(wm + i * 16 + arow) * ROWB + ak * 16;
            LDSM4(ah, Ah + off);
            LDSM4(al, Al + off);
            #pragma unroll
            for (int j = 0; j < 4; ++j) {
                uint32_t* pbh = &bh[j >> 1][(j & 1) * 2];
                uint32_t* pbl = &bl[j >> 1][(j & 1) * 2];
                MMA16816(acc[i][j], ah, pbh);
                MMA16816(acc[i][j], ah, pbl);
                MMA16816(acc[i][j], al, pbh);
            }
        }
        __syncthreads();
        if (c + 3 < NC) issue(st, c + 3);
        CP_COMMIT();
    }

    float* dst = &g_part[ks][0];
    const int r0 = lane >> 2, cc0 = (lane & 3) * 2;
    #pragma unroll
    for (int i = 0; i < 4; ++i) {
        #pragma unroll
        for (int j = 0; j < 4; ++j) {
            int row = bm + wm + i * 16 + r0;
            int col = bn + wn + j * 8 + cc0;
            *(float2*)(dst + (size_t)row * NPAD + col) =
                make_float2(acc[i][j][0], acc[i][j][1]);
            *(float2*)(dst + (size_t)(row + 8) * NPAD + col) =
                make_float2(acc[i][j][2], acc[i][j][3]);
        }
    }

    // ---- group combine: last of the 4 K-split blocks writes output ----
    __threadfence();
    __syncthreads();
    __shared__ int is_last;
    if (tid == 0) {
        unsigned old = atomicAdd(&g_cnt_grp[g_id & 31], 1u);
        is_last = (old == 3u);
        if (is_last) {
            while (atomicAdd(&g_cnt_r, 0u) < 128u) __nanosleep(64);
        }
    }
    __syncthreads();
    if (!is_last) return;
    __threadfence();

    const int c4s = bn >> 2;                               // float4 col start
    const int c4e = ((bn + 128 < NDIM) ? (bn + 128) : NDIM) >> 2;
    const int nc4 = c4e - c4s;                             // 32 or 26
    for (int it = tid; it < 128 * nc4; it += 256) {
        int rl = it / nc4, q = it - rl * nc4;
        int row = bm + rl;
        int c4 = c4s + q;
        size_t o4 = (size_t)row * (NPAD / 4) + c4;
        float4 p0 = ((const float4*)g_part[0])[o4];
        float4 p1 = ((const float4*)g_part[1])[o4];
        float4 p2 = ((const float4*)g_part[2])[o4];
        float4 p3 = ((const float4*)g_part[3])[o4];
        float4 rv = ((const float4*)g_r)[c4];
        float4 bv = ((const float4*)bias)[c4];
        float4 v;
        v.x = (p0.x + p1.x) + (p2.x + p3.x) - rv.x + bv.x;
        v.y = (p0.y + p1.y) + (p2.y + p3.y) - rv.y + bv.y;
        v.z = (p0.z + p1.z) + (p2.z + p3.z) - rv.z + bv.z;
        v.w = (p0.w + p1.w) + (p2.w + p3.w) - rv.w + bv.w;
        ((float4*)out)[(size_t)row * (NDIM / 4) + c4] = v;
    }
}

// ---------------------------------------------------------------------------
// Launch: x, sketch_mu, g, noise, W, b, h(unused), t
// ---------------------------------------------------------------------------
extern "C" void kernel_launch(void* const* d_in, const int* in_sizes, int n_in,
                              void* d_out, int out_size)
{
    const float* x     = (const float*)d_in[0];
    const float* sk    = (const float*)d_in[1];
    const float* g     = (const float*)d_in[2];
    const float* noise = (const float*)d_in[3];
    const float* W     = (const float*)d_in[4];
    const float* bias  = (const float*)d_in[5];
    const int*   tptr  = (const int*)d_in[7];
    float* out = (float*)d_out;

    int N = in_sizes[5];

    float s = 1.0f / (1.0f + 1e-6f) / sqrtf(3.0f / 8.0f + 1e-6f);

    cudaFuncSetAttribute(fused_kernel, cudaFuncAttributeMaxDynamicSharedMemorySize,
                         SMEM_GEMM);

    prep_kernel<<<3072, 256>>>(W, x, N, s);
    fused_kernel<<<256, 256, SMEM_GEMM>>>(sk, noise, x, g, tptr, bias, out, s);
}

// round 17
// speedup vs baseline: 1.0399x; 1.0399x over previous
#include <cuda_runtime.h>
#include <cuda_bf16.h>
#include <math.h>
#include <stdint.h>

// ===========================================================================
// ZorroPP reduced:
//   mu[c] = g[c]*((1-l)*rowmean(sk[c,:]) + (1/t)*g[c]*colsum_x[c]*(C/M) + 0.01*rowmean(noise[c,:]))
//   out   = (s*x) @ W - s*(mu^T W) + b      (rank-1 mu correction pulled out)
// GEMM: HMMA m16n8k16 bf16 hi/lo split (3 products) = emulated fp32.
// R17 = R15 (best 82.4us) with prep's W-tile reads vectorized to float4
// (W rows are 16B-aligned: 4000B stride; N=1000 -> col-aligned float4 is
// all-in or all-out of bounds).
// ===========================================================================

#define BDIM 512
#define CDIM 4096
#define NDIM 1000
#define NPAD 1024
#define MSK  8192
#define KSPLIT 4
#define KSLICE (CDIM / KSPLIT)   // 1024
#define KCH 16
#define NC (KSLICE / KCH)        // 64 chunks per gemm block

__device__ float g_mu[CDIM];
__device__ __nv_bfloat16 g_xhi[BDIM * CDIM];
__device__ __nv_bfloat16 g_xlo[BDIM * CDIM];
__device__ __nv_bfloat16 g_wthi[NPAD * CDIM];
__device__ __nv_bfloat16 g_wtlo[NPAD * CDIM];
__device__ float g_part[KSPLIT][BDIM * NPAD];

// ---------------------------------------------------------------------------
// PTX helpers (baseline sm_80+; compute_103-safe)
// ---------------------------------------------------------------------------
__device__ __forceinline__ uint32_t smem_u32(const void* p) {
    uint32_t a;
    asm("{ .reg .u64 t; cvta.to.shared.u64 t, %1; cvt.u32.u64 %0, t; }"
        : "=r"(a) : "l"(p));
    return a;
}
__device__ __forceinline__ void cpasync16(uint32_t sdst, const void* gsrc) {
    asm volatile("cp.async.cg.shared.global [%0], [%1], 16;"
                 :: "r"(sdst), "l"(gsrc) : "memory");
}
#define CP_COMMIT() asm volatile("cp.async.commit_group;" ::: "memory")
#define CP_WAIT2()  asm volatile("cp.async.wait_group 2;" ::: "memory")

#define LDSM4(r, addr)                                                        \
    asm volatile("ldmatrix.sync.aligned.m8n8.x4.shared.b16 {%0,%1,%2,%3}, [%4];" \
                 : "=r"((r)[0]), "=r"((r)[1]), "=r"((r)[2]), "=r"((r)[3])     \
                 : "r"(addr))

#define MMA16816(d, a, b)                                                     \
    asm volatile("mma.sync.aligned.m16n8k16.row.col.f32.bf16.bf16.f32 "      \
                 "{%0,%1,%2,%3}, {%4,%5,%6,%7}, {%8,%9}, {%0,%1,%2,%3};"     \
                 : "+f"((d)[0]), "+f"((d)[1]), "+f"((d)[2]), "+f"((d)[3])     \
                 : "r"((a)[0]), "r"((a)[1]), "r"((a)[2]), "r"((a)[3]),        \
                   "r"((b)[0]), "r"((b)[1]))

// ---------------------------------------------------------------------------
// Kernel 1 (PREP): [0,1024) W->W^T hi/lo (64x64 tiles, float4 reads);
//                  [1024,3072) x*s hi/lo
// ---------------------------------------------------------------------------
__global__ __launch_bounds__(256) void prep_kernel(
    const float* __restrict__ W, const float* __restrict__ x, int N, float s)
{
    __shared__ float tile[64][65];
    int bid = blockIdx.x;
    if (bid < 1024) {
        int k0 = (bid & 63) * 64, n0 = (bid >> 6) * 64;
        // load: 64 rows x 16 float4 = 1024 float4s, 4 per thread.
        // W rows are 16B-aligned (N*4 = 4000 % 16 == 0); col-aligned float4
        // is fully in-bounds iff col < N (N % 4 == 0).
        #pragma unroll
        for (int p = 0; p < 4; ++p) {
            int idx = p * 256 + threadIdx.x;      // 0..1023
            int row = idx >> 4;                   // k within tile
            int q4  = idx & 15;                   // float4 within row
            int col = n0 + q4 * 4;
            float4 v = make_float4(0.f, 0.f, 0.f, 0.f);
            if (col < N)
                v = *(const float4*)(W + (size_t)(k0 + row) * N + col);
            tile[row][q4 * 4 + 0] = v.x;
            tile[row][q4 * 4 + 1] = v.y;
            tile[row][q4 * 4 + 2] = v.z;
            tile[row][q4 * 4 + 3] = v.w;
        }
        __syncthreads();
        int tx = threadIdx.x & 31, ty = threadIdx.x >> 5;
        #pragma unroll
        for (int r = 0; r < 8; ++r) {
            int nn = ty + r * 8;
            float v0 = tile[tx * 2][nn];
            float v1 = tile[tx * 2 + 1][nn];
            __nv_bfloat16 h0 = __float2bfloat16(v0);
            __nv_bfloat16 h1 = __float2bfloat16(v1);
            __nv_bfloat16 l0 = __float2bfloat16(v0 - __bfloat162float(h0));
            __nv_bfloat16 l1 = __float2bfloat16(v1 - __bfloat162float(h1));
            size_t o = (size_t)(n0 + nn) * CDIM + k0 + tx * 2;
            *(__nv_bfloat162*)&g_wthi[o] = __halves2bfloat162(h0, h1);
            *(__nv_bfloat162*)&g_wtlo[o] = __halves2bfloat162(l0, l1);
        }
    } else {
        int i4 = (bid - 1024) * 256 + threadIdx.x;
        float4 v = ((const float4*)x)[i4];
        float a0 = v.x * s, a1 = v.y * s, a2 = v.z * s, a3 = v.w * s;
        __nv_bfloat16 h0 = __float2bfloat16(a0), h1 = __float2bfloat16(a1);
        __nv_bfloat16 h2 = __float2bfloat16(a2), h3 = __float2bfloat16(a3);
        __nv_bfloat16 l0 = __float2bfloat16(a0 - __bfloat162float(h0));
        __nv_bfloat16 l1 = __float2bfloat16(a1 - __bfloat162float(h1));
        __nv_bfloat16 l2 = __float2bfloat16(a2 - __bfloat162float(h2));
        __nv_bfloat16 l3 = __float2bfloat16(a3 - __bfloat162float(h3));
        __nv_bfloat162* ph = (__nv_bfloat162*)(g_xhi + (size_t)i4 * 4);
        __nv_bfloat162* pl = (__nv_bfloat162*)(g_xlo + (size_t)i4 * 4);
        ph[0] = __halves2bfloat162(h0, h1);
        ph[1] = __halves2bfloat162(h2, h3);
        pl[0] = __halves2bfloat162(l0, l1);
        pl[1] = __halves2bfloat162(l2, l3);
    }
}

// ---------------------------------------------------------------------------
// Kernel 2 (FUSED): blocks [0,128) = GEMM 128x128 tile, full K-slice 1024,
//                   3-stage cp.async (KCH=16, ROWB=48);
//                   blocks [128,256) = mu, 32 channels each (ldcs streaming).
// ---------------------------------------------------------------------------
#define ROWB 48
#define TILE_B (128 * ROWB)          // 6144
#define STAGE_B (4 * TILE_B)         // 24576
#define SMEM_GEMM (3 * STAGE_B)      // 73728 -> 2 blocks/SM

__global__ __launch_bounds__(256, 2) void fused_kernel(
    const float* __restrict__ sk, const float* __restrict__ noise,
    const float* __restrict__ x, const float* __restrict__ g,
    const int* __restrict__ tptr)
{
    extern __shared__ char smem[];
    const int tid = threadIdx.x, wid = tid >> 5, lane = tid & 31;
    const int bid = blockIdx.x;

    if (bid >= 128) {
        // ================= mu block: 32 channels (proven ldcs path) ========
        const int c0 = (bid - 128) * 32;
        __shared__ float ps[8][33];
        __shared__ float colsum_s[32];
        {   // coalesced colsum of x
            int ch = tid & 31, rg = tid >> 5;
            float cs = 0.f;
            #pragma unroll 8
            for (int r = rg; r < BDIM; r += 8)
                cs += x[(size_t)r * CDIM + c0 + ch];
            ps[rg][ch] = cs;
        }
        __syncthreads();
        if (tid < 32) {
            float v = 0.f;
            #pragma unroll
            for (int j = 0; j < 8; ++j) v += ps[j][tid];
            colsum_s[tid] = v;
        }
        __syncthreads();

        int ti = *tptr;
        float tf = (ti > 0 && ti < 1000000) ? (float)ti : __int_as_float(ti);
        float lam = 1.f - expf(-tf / 64.f);
        float kap = 1.f / tf;
        const float inv_m = 1.f / (float)MSK;
        const float mean_counts = (float)CDIM * inv_m;

        #pragma unroll
        for (int j = 0; j < 4; ++j) {
            int c = c0 + wid * 4 + j;
            const float4* sr = (const float4*)(sk + (size_t)c * MSK);
            const float4* nr = (const float4*)(noise + (size_t)c * MSK);
            float s1 = 0.f, s2 = 0.f;
            #pragma unroll 8
            for (int i = lane; i < MSK / 4; i += 32) {
                float4 a = __ldcs(&sr[i]);
                float4 b = __ldcs(&nr[i]);
                s1 += (a.x + a.y) + (a.z + a.w);
                s2 += (b.x + b.y) + (b.z + b.w);
            }
            #pragma unroll
            for (int off = 16; off > 0; off >>= 1) {
                s1 += __shfl_xor_sync(0xFFFFFFFFu, s1, off);
                s2 += __shfl_xor_sync(0xFFFFFFFFu, s2, off);
            }
            if (lane == 0) {
                float gc = g[c];
                float mean_sk = (1.f - lam) * (s1 * inv_m)
                              + kap * gc * colsum_s[wid * 4 + j] * mean_counts
                              + 0.01f * (s2 * inv_m);
                g_mu[c] = gc * mean_sk;
            }
        }
        return;
    }

    // ================= GEMM block (3-stage, KCH=16) =================
    const uint32_t sb = smem_u32(smem);
    const int g_id = bid;
    const int bn = (g_id & 7) * 128;
    const int bm = ((g_id >> 3) & 3) * 128;
    const int ks = g_id >> 5;
    const int kb0 = ks * KSLICE;

    const __nv_bfloat16* base[4] = {
        g_xhi  + (size_t)bm * CDIM + kb0,
        g_xlo  + (size_t)bm * CDIM + kb0,
        g_wthi + (size_t)bn * CDIM + kb0,
        g_wtlo + (size_t)bn * CDIM + kb0
    };
    // per stage: 4 tiles x 128 rows x 2 x 16B segments = 1024 chunks = 4/thread
    const __nv_bfloat16* gp[4];
    uint32_t so[4];
    #pragma unroll
    for (int t = 0; t < 4; ++t) {
        int idx = t * 256 + tid;          // 0..1023
        int tile = idx >> 8;              // 0..3
        int j = idx & 255;
        int row = j >> 1, seg = j & 1;    // row 0..127, 16B segment 0..1
        gp[t] = base[tile] + (size_t)row * CDIM + seg * 8;
        so[t] = tile * TILE_B + row * ROWB + seg * 16;
    }

    auto issue = [&](int stage, int c) {
        uint32_t s0 = sb + stage * STAGE_B;
        #pragma unroll
        for (int t = 0; t < 4; ++t)
            cpasync16(s0 + so[t], gp[t] + c * KCH);
    };

    issue(0, 0); CP_COMMIT();
    issue(1, 1); CP_COMMIT();
    issue(2, 2); CP_COMMIT();

    const int wm = (wid >> 2) * 64;
    const int wn = (wid & 3) * 32;

    float acc[4][4][4];
    #pragma unroll
    for (int i = 0; i < 4; ++i)
        #pragma unroll
        for (int j = 0; j < 4; ++j)
            #pragma unroll
            for (int q = 0; q < 4; ++q) acc[i][j][q] = 0.f;

    const int arow = lane & 15;
    const int ak   = lane >> 4;
    const int brow = (lane & 7) + ((lane >> 4) << 3);
    const int bk   = (lane >> 3) & 1;

    for (int c = 0; c < NC; ++c) {
        int st = c % 3;
        CP_WAIT2();
        __syncthreads();

        uint32_t Ah = sb + st * STAGE_B;
        uint32_t Al = Ah + TILE_B;
        uint32_t Bh = Ah + 2 * TILE_B;
        uint32_t Bl = Ah + 3 * TILE_B;

        // single k16 step per chunk
        uint32_t bh[2][4], bl[2][4];
        #pragma unroll
        for (int p = 0; p < 2; ++p) {
            uint32_t off = (uint32_t)(wn + p * 16 + brow) * ROWB + bk * 16;
            LDSM4(bh[p], Bh + off);
            LDSM4(bl[p], Bl + off);
        }
        #pragma unroll
        for (int i = 0; i < 4; ++i) {
            uint32_t ah[4], al[4];
            uint32_t off = (uint32_t)(wm + i * 16 + arow) * ROWB + ak * 16;
            LDSM4(ah, Ah + off);
            LDSM4(al, Al + off);
            #pragma unroll
            for (int j = 0; j < 4; ++j) {
                uint32_t* pbh = &bh[j >> 1][(j & 1) * 2];
                uint32_t* pbl = &bl[j >> 1][(j & 1) * 2];
                MMA16816(acc[i][j], ah, pbh);
                MMA16816(acc[i][j], ah, pbl);
                MMA16816(acc[i][j], al, pbh);
            }
        }
        __syncthreads();
        if (c + 3 < NC) issue(st, c + 3);
        CP_COMMIT();
    }

    float* dst = &g_part[ks][0];
    const int r0 = lane >> 2, cc0 = (lane & 3) * 2;
    #pragma unroll
    for (int i = 0; i < 4; ++i) {
        #pragma unroll
        for (int j = 0; j < 4; ++j) {
            int row = bm + wm + i * 16 + r0;
            int col = bn + wn + j * 8 + cc0;
            *(float2*)(dst + (size_t)row * NPAD + col) =
                make_float2(acc[i][j][0], acc[i][j][1]);
            *(float2*)(dst + (size_t)(row + 8) * NPAD + col) =
                make_float2(acc[i][j][2], acc[i][j][3]);
        }
    }
}

// ---------------------------------------------------------------------------
// Kernel 3: gemv + combine merged (unchanged from R15, passing).
// ---------------------------------------------------------------------------
__global__ __launch_bounds__(256) void gemv_combine_kernel(
    const float* __restrict__ bias, float* __restrict__ out, float s)
{
    __shared__ float mus[CDIM];
    __shared__ float r_s[8];
    int tid = threadIdx.x, wid = tid >> 5, lane = tid & 31;
    #pragma unroll
    for (int q = 0; q < CDIM / 256; ++q)
        mus[q * 256 + tid] = g_mu[q * 256 + tid];
    __syncthreads();

    int n = blockIdx.x * 8 + wid;
    const uint4* hp = (const uint4*)(g_wthi + (size_t)n * CDIM);
    const uint4* lp = (const uint4*)(g_wtlo + (size_t)n * CDIM);
    float acc = 0.f;
    #pragma unroll 4
    for (int q = 0; q < 16; ++q) {
        int idx = lane + q * 32;
        uint4 h = __ldcs(&hp[idx]), l = __ldcs(&lp[idx]);
        const float4* mp = (const float4*)(mus + idx * 8);
        float4 m0 = mp[0], m1 = mp[1];
        float2 h0 = __bfloat1622float2(*(__nv_bfloat162*)&h.x);
        float2 h1 = __bfloat1622float2(*(__nv_bfloat162*)&h.y);
        float2 h2 = __bfloat1622float2(*(__nv_bfloat162*)&h.z);
        float2 h3 = __bfloat1622float2(*(__nv_bfloat162*)&h.w);
        float2 l0 = __bfloat1622float2(*(__nv_bfloat162*)&l.x);
        float2 l1 = __bfloat1622float2(*(__nv_bfloat162*)&l.y);
        float2 l2 = __bfloat1622float2(*(__nv_bfloat162*)&l.z);
        float2 l3 = __bfloat1622float2(*(__nv_bfloat162*)&l.w);
        acc += m0.x * (h0.x + l0.x) + m0.y * (h0.y + l0.y)
             + m0.z * (h1.x + l1.x) + m0.w * (h1.y + l1.y)
             + m1.x * (h2.x + l2.x) + m1.y * (h2.y + l2.y)
             + m1.z * (h3.x + l3.x) + m1.w * (h3.y + l3.y);
    }
    #pragma unroll
    for (int off = 16; off > 0; off >>= 1)
        acc += __shfl_xor_sync(0xFFFFFFFFu, acc, off);
    if (lane == 0) r_s[wid] = acc * s;
    __syncthreads();

    float rf[8];
    #pragma unroll
    for (int j = 0; j < 8; ++j) rf[j] = r_s[j];
    float bf[8];
    #pragma unroll
    for (int j = 0; j < 8; ++j) bf[j] = bias[blockIdx.x * 8 + j];

    #pragma unroll
    for (int k = 0; k < 2; ++k) {
        int m = tid + k * 256;
        size_t o4 = (size_t)m * (NPAD / 4) + blockIdx.x * 2;
        float4 v0, v1;
        {
            float4 p0 = ((const float4*)g_part[0])[o4];
            float4 p1 = ((const float4*)g_part[1])[o4];
            float4 p2 = ((const float4*)g_part[2])[o4];
            float4 p3 = ((const float4*)g_part[3])[o4];
            v0.x = (p0.x + p1.x) + (p2.x + p3.x) - rf[0] + bf[0];
            v0.y = (p0.y + p1.y) + (p2.y + p3.y) - rf[1] + bf[1];
            v0.z = (p0.z + p1.z) + (p2.z + p3.z) - rf[2] + bf[2];
            v0.w = (p0.w + p1.w) + (p2.w + p3.w) - rf[3] + bf[3];
        }
        {
            float4 p0 = ((const float4*)g_part[0])[o4 + 1];
            float4 p1 = ((const float4*)g_part[1])[o4 + 1];
            float4 p2 = ((const float4*)g_part[2])[o4 + 1];
            float4 p3 = ((const float4*)g_part[3])[o4 + 1];
            v1.x = (p0.x + p1.x) + (p2.x + p3.x) - rf[4] + bf[4];
            v1.y = (p0.y + p1.y) + (p2.y + p3.y) - rf[5] + bf[5];
            v1.z = (p0.z + p1.z) + (p2.z + p3.z) - rf[6] + bf[6];
            v1.w = (p0.w + p1.w) + (p2.w + p3.w) - rf[7] + bf[7];
        }
        ((float4*)out)[(size_t)m * 250 + blockIdx.x * 2]     = v0;
        ((float4*)out)[(size_t)m * 250 + blockIdx.x * 2 + 1] = v1;
    }
}

// ---------------------------------------------------------------------------
// Launch: x, sketch_mu, g, noise, W, b, h(unused), t
// ---------------------------------------------------------------------------
extern "C" void kernel_launch(void* const* d_in, const int* in_sizes, int n_in,
                              void* d_out, int out_size)
{
    const float* x     = (const float*)d_in[0];
    const float* sk    = (const float*)d_in[1];
    const float* g     = (const float*)d_in[2];
    const float* noise = (const float*)d_in[3];
    const float* W     = (const float*)d_in[4];
    const float* bias  = (const float*)d_in[5];
    const int*   tptr  = (const int*)d_in[7];
    float* out = (float*)d_out;

    int N = in_sizes[5];

    float s = 1.0f / (1.0f + 1e-6f) / sqrtf(3.0f / 8.0f + 1e-6f);

    cudaFuncSetAttribute(fused_kernel, cudaFuncAttributeMaxDynamicSharedMemorySize,
                         SMEM_GEMM);

    prep_kernel<<<3072, 256>>>(W, x, N, s);
    fused_kernel<<<256, 256, SMEM_GEMM>>>(sk, noise, x, g, tptr);
    gemv_combine_kernel<<<125, 256>>>(bias, out, s);
}